// round 6
// baseline (speedup 1.0000x reference)
#include <cuda_runtime.h>
#include <cstdint>

#define Nn 2
#define Cc 8
#define CPT 4                  // channels per thread (z-split)
#define Hh 256
#define Ww 512
#define KK 9
#define PADW 4
#define BH 8
#define BW 32
#define TX 8                   // threads along w, each covers 4 outputs
#define ROWS (BH + 8)          // 16
#define COLS (BW + 8)          // 40
#define NTHREADS (TX * BH * 2) // 128
#define TAPCHUNKS (KK * BH * (BW / 4))   // 576 float4 chunks per i-row tile

__device__ __forceinline__ void cp16(uint32_t smem_dst, const void* gmem_src) {
    asm volatile("cp.async.cg.shared.global [%0], [%1], 16;"
                 :: "r"(smem_dst), "l"(gmem_src));
}

__global__ __launch_bounds__(NTHREADS, 5)
void dfl_kernel(const float* __restrict__ x,
                const float* __restrict__ filt,
                const float* __restrict__ bias,
                float* __restrict__ out)
{
    __shared__ __align__(16) float sx[Cc][ROWS][COLS];        // 20,480 B
    __shared__ __align__(16) float staps[2][KK][BH][BW];      // 18,432 B

    const int n  = blockIdx.z;
    const int h0 = blockIdx.y * BH;
    const int w0 = blockIdx.x * BW;
    const int tid = (threadIdx.z * BH + threadIdx.y) * TX + threadIdx.x;

    const float* ftile = filt + (((size_t)n * (KK * KK)) * Hh + h0) * Ww + w0;
    const size_t tap_stride = (size_t)Hh * Ww;

    // ---- prologue: start async tap fetch for i=0 immediately ----
    #pragma unroll 1
    for (int g = tid; g < TAPCHUNKS; g += NTHREADS) {
        int q = g & 7;              // 0..7 -> 4-float group
        int r = (g >> 3) & 7;       // 0..7 -> h row
        int j = g >> 6;             // 0..8 -> tap col index
        cp16((uint32_t)__cvta_generic_to_shared(&staps[0][j][r][q * 4]),
             ftile + (size_t)j * tap_stride + (size_t)r * Ww + q * 4);
    }
    asm volatile("cp.async.commit_group;");

    // ---- fill shared x tile (zero-padded halo); overlaps with G0 ----
    const float* xn = x + (size_t)n * Cc * Hh * Ww;
    #pragma unroll 1
    for (int g = tid; g < Cc * ROWS * 10; g += NTHREADS) {
        int q  = g % 10;
        int rc = g / 10;
        int r  = rc % ROWS;
        int c  = rc / ROWS;
        int gh = h0 - PADW + r;
        int gw = w0 - PADW + q * 4;
        float4 v = make_float4(0.f, 0.f, 0.f, 0.f);
        if (gh >= 0 && gh < Hh) {
            const float* row = xn + ((size_t)c * Hh + gh) * Ww;
            if (gw >= 0 && gw + 3 < Ww) {
                v = *reinterpret_cast<const float4*>(row + gw);
            } else {
                float t0 = (gw + 0 >= 0 && gw + 0 < Ww) ? row[gw + 0] : 0.f;
                float t1 = (gw + 1 >= 0 && gw + 1 < Ww) ? row[gw + 1] : 0.f;
                float t2 = (gw + 2 >= 0 && gw + 2 < Ww) ? row[gw + 2] : 0.f;
                float t3 = (gw + 3 >= 0 && gw + 3 < Ww) ? row[gw + 3] : 0.f;
                v = make_float4(t0, t1, t2, t3);
            }
        }
        *reinterpret_cast<float4*>(&sx[c][r][q * 4]) = v;
    }

    // ---- per-thread output coords ----
    const int hl = threadIdx.y;          // 0..7
    const int h  = h0 + hl;
    const int wl = threadIdx.x * 4;      // 0..28
    const int w  = w0 + wl;
    const int c0 = threadIdx.z * CPT;    // 0 or 4

    float4 acc[CPT];
    {
        float4 b = *reinterpret_cast<const float4*>(bias + ((size_t)n * Hh + h) * Ww + w);
        #pragma unroll
        for (int c = 0; c < CPT; c++) acc[c] = b;
    }

    // ---- main loop: compute tile i while cp.async streams tile i+1 ----
    #pragma unroll 1
    for (int i = 0; i < KK; i++) {
        if (i < KK - 1) {
            const float* fnext = ftile + (size_t)(i + 1) * KK * tap_stride;
            int buf = (i + 1) & 1;
            #pragma unroll 1
            for (int g = tid; g < TAPCHUNKS; g += NTHREADS) {
                int q = g & 7;
                int r = (g >> 3) & 7;
                int j = g >> 6;
                cp16((uint32_t)__cvta_generic_to_shared(&staps[buf][j][r][q * 4]),
                     fnext + (size_t)j * tap_stride + (size_t)r * Ww + q * 4);
            }
            asm volatile("cp.async.commit_group;");
            asm volatile("cp.async.wait_group 1;");   // tile i complete
        } else {
            asm volatile("cp.async.wait_group 0;");   // last tile complete
        }
        __syncthreads();   // tap tile i visible to all; sx ready (first iter)

        // taps for this i-row: 9 x LDS.128, shared across this half's channels
        const int cur = i & 1;
        float4 f[KK];
        #pragma unroll
        for (int j = 0; j < KK; j++)
            f[j] = *reinterpret_cast<const float4*>(&staps[cur][j][hl][wl]);

        #pragma unroll
        for (int c = 0; c < CPT; c++) {
            const float* sp = &sx[c0 + c][hl + i][wl];
            float4 x0 = *reinterpret_cast<const float4*>(sp);
            float4 x1 = *reinterpret_cast<const float4*>(sp + 4);
            float4 x2 = *reinterpret_cast<const float4*>(sp + 8);
            float xw[12] = { x0.x, x0.y, x0.z, x0.w,
                             x1.x, x1.y, x1.z, x1.w,
                             x2.x, x2.y, x2.z, x2.w };
            #pragma unroll
            for (int j = 0; j < KK; j++) {
                acc[c].x = fmaf(xw[j + 0], f[j].x, acc[c].x);
                acc[c].y = fmaf(xw[j + 1], f[j].y, acc[c].y);
                acc[c].z = fmaf(xw[j + 2], f[j].z, acc[c].z);
                acc[c].w = fmaf(xw[j + 3], f[j].w, acc[c].w);
            }
        }
        __syncthreads();   // all reads of buf done before it is overwritten
    }

    // ---- store (streaming hint: keep L2 for x/filters) ----
    float* obase = out + (((size_t)n * Cc + c0) * Hh + h) * Ww + w;
    #pragma unroll
    for (int c = 0; c < CPT; c++)
        __stcs(reinterpret_cast<float4*>(obase + (size_t)c * Hh * Ww), acc[c]);
}

extern "C" void kernel_launch(void* const* d_in, const int* in_sizes, int n_in,
                              void* d_out, int out_size)
{
    const float* x    = (const float*)d_in[0];   // x_in  (2,8,256,512)
    const float* filt = (const float*)d_in[1];   // filters (2,81,256,512)
    const float* bias = (const float*)d_in[2];   // filters_biases (2,1,256,512)
    float* out = (float*)d_out;

    dim3 grid(Ww / BW, Hh / BH, Nn);   // (16, 32, 2) = 1024 CTAs
    dim3 block(TX, BH, 2);             // (8, 8, 2) = 128 threads
    dfl_kernel<<<grid, block>>>(x, filt, bias, out);
}